// round 9
// baseline (speedup 1.0000x reference)
#include <cuda_runtime.h>

#define HN 4096

constexpr int TH = 64;                     // output rows per warp-tile
constexpr int OUTW = 112;                  // output cols per warp strip
constexpr int NSTRIPS = 37;
constexpr int WPB = 4;
constexpr int NTILES = NSTRIPS * (HN / TH);   // 2368
constexpr int NBLK = NTILES / WPB;            // 592 = 4 * 148
constexpr int N_INT = 35 * 62;                // 2170 interior tiles

__device__ double g_accs[8 * 16];
__device__ unsigned g_done;

static __device__ __forceinline__ float4 ld4p(const float* p, bool v) {
    float4 r = make_float4(0.f, 0.f, 0.f, 0.f);
    if (v) r = *reinterpret_cast<const float4*>(p);
    return r;
}

// 4-tap window sum over columns: g[c] = v[c-1]+v[c]+v[c+1]+v[c+2]
static __device__ __forceinline__ float4 hwin(float4 v, float vl, float vr0, float vr1) {
    float4 g;
    g.x = vl + v.x + v.y + v.z;
    g.y = g.x - vl + v.w;
    g.z = g.y - v.x + vr0;
    g.w = g.z - v.y + vr1;
    return g;
}

static __device__ __forceinline__ float maskf(float x, unsigned m) {
    return __uint_as_float(__float_as_uint(x) & m);
}

template<bool EDGE>
static __device__ __forceinline__ float tile_compute(
    const float* __restrict__ X, const float* __restrict__ Y,
    int strip, int tyt, int lane, int tid,
    float4 (*sc1)[128], float4 (*sc2)[128])
{
    const int ty0 = tyt * TH;
    const long col0 = (long)strip * OUTW - 8 + 4 * lane;
    const bool ld_ok = EDGE ? ((col0 >= 0) && (col0 + 3 < HN)) : true;
    const unsigned mCb = EDGE ? ((lane >= 1 && lane <= 30 && ld_ok) ? ~0u : 0u) : ~0u;
    const float mO = ((lane >= 2 && lane <= 29) && ld_ok) ? 1.f : 0.f;
    const float mOn = -mO;
    const int i0 = ty0 - 8;   // multiple of 8 (TH=64)

    // base pointer: row loaded at group-local step S is pX + S*HN (row i0+8+g)
    const float* pX = X + col0 + (long)(i0 + 8) * HN;
    const float* pY = Y + col0 + (long)(i0 + 8) * HN;

    // 8-deep raw-row rings: row r lives in slot r&7
    float4 rxr[8], ryr[8];
    const float4 z4 = make_float4(0.f, 0.f, 0.f, 0.f);
    rxr[0] = rxr[1] = rxr[2] = rxr[3] = z4;
    ryr[0] = ryr[1] = ryr[2] = ryr[3] = z4;
#pragma unroll
    for (int k = 0; k < 4; ++k) {   // prefill rows i0+4..i0+7 -> slots 4..7
        bool v = EDGE ? (ld_ok && (unsigned)(i0 + 4 + k) < HN) : true;
        rxr[4 + k] = ld4p(pX + (long)(k - 4) * HN, v);
        ryr[4 + k] = ld4p(pY + (long)(k - 4) * HN, v);
    }
    // zero the centered-value rings (per-thread private smem slots)
#pragma unroll
    for (int s = 0; s < 4; ++s) { sc1[s][tid] = z4; sc2[s][tid] = z4; }

    float4 Vx = z4, Vy = z4, Vi = z4, Vj = z4, Vc = z4;
    float acc = 0.f;   // accumulates -L over valid output pixels

// One row-step. S in 0..7 (compile-time). IROW = absolute row index i (only
// used under EDGE). DO_OUT / DO_LOAD compile-time flags.
#define STEP(S, IROW, DO_OUT, DO_LOAD) do {                                      \
    /* evict-c from smem, early (written 4 steps ago, same thread) */            \
    float4 o1 = sc1[((S) + 2) & 3][tid];                                         \
    float4 o2 = sc2[((S) + 2) & 3][tid];                                         \
    /* evict raw row i (slot S), then reuse slot for row i+8 */                  \
    float4 xo = rxr[(S)], yo = ryr[(S)];                                         \
    if (DO_LOAD) {                                                               \
        bool v = EDGE ? (ld_ok && (unsigned)((IROW) + 8) < HN) : true;           \
        rxr[(S)] = ld4p(pX + (long)(S) * HN, v);                                 \
        ryr[(S)] = ld4p(pY + (long)(S) * HN, v);                                 \
    }                                                                            \
    float4 xc = rxr[((S) + 4) & 7], yc = ryr[((S) + 4) & 7];  /* row i+4 */      \
    Vx.x += xc.x - xo.x; Vx.y += xc.y - xo.y;                                    \
    Vx.z += xc.z - xo.z; Vx.w += xc.w - xo.w;                                    \
    Vy.x += yc.x - yo.x; Vy.y += yc.y - yo.y;                                    \
    Vy.z += yc.z - yo.z; Vy.w += yc.w - yo.w;                                    \
    float4 x2 = rxr[((S) + 2) & 7], y2 = ryr[((S) + 2) & 7];  /* row i+2 */      \
    float vlx  = __shfl_up_sync(0xffffffffu, Vx.w, 1);                           \
    float vrx0 = __shfl_down_sync(0xffffffffu, Vx.x, 1);                         \
    float vrx1 = __shfl_down_sync(0xffffffffu, Vx.y, 1);                         \
    float vly  = __shfl_up_sync(0xffffffffu, Vy.w, 1);                           \
    float vry0 = __shfl_down_sync(0xffffffffu, Vy.x, 1);                         \
    float vry1 = __shfl_down_sync(0xffffffffu, Vy.y, 1);                         \
    float4 mx = hwin(Vx, vlx, vrx0, vrx1);   /* 16*mu at row i+2 */              \
    float4 my = hwin(Vy, vly, vry0, vry1);                                       \
    unsigned rmask = EDGE ? (((unsigned)((IROW) + 2) < HN) ? mCb : 0u) : ~0u;    \
    float4 c1, c2;                                                               \
    c1.x = maskf(fmaf(mx.x, -0.0625f, x2.x), rmask);                             \
    c1.y = maskf(fmaf(mx.y, -0.0625f, x2.y), rmask);                             \
    c1.z = maskf(fmaf(mx.z, -0.0625f, x2.z), rmask);                             \
    c1.w = maskf(fmaf(mx.w, -0.0625f, x2.w), rmask);                             \
    c2.x = maskf(fmaf(my.x, -0.0625f, y2.x), rmask);                             \
    c2.y = maskf(fmaf(my.y, -0.0625f, y2.y), rmask);                             \
    c2.z = maskf(fmaf(my.z, -0.0625f, y2.z), rmask);                             \
    c2.w = maskf(fmaf(my.w, -0.0625f, y2.w), rmask);                             \
    sc1[((S) + 2) & 3][tid] = c1;                                                \
    sc2[((S) + 2) & 3][tid] = c2;                                                \
    Vi.x = fmaf(c1.x, c1.x, fmaf(o1.x, -o1.x, Vi.x));                            \
    Vi.y = fmaf(c1.y, c1.y, fmaf(o1.y, -o1.y, Vi.y));                            \
    Vi.z = fmaf(c1.z, c1.z, fmaf(o1.z, -o1.z, Vi.z));                            \
    Vi.w = fmaf(c1.w, c1.w, fmaf(o1.w, -o1.w, Vi.w));                            \
    Vj.x = fmaf(c2.x, c2.x, fmaf(o2.x, -o2.x, Vj.x));                            \
    Vj.y = fmaf(c2.y, c2.y, fmaf(o2.y, -o2.y, Vj.y));                            \
    Vj.z = fmaf(c2.z, c2.z, fmaf(o2.z, -o2.z, Vj.z));                            \
    Vj.w = fmaf(c2.w, c2.w, fmaf(o2.w, -o2.w, Vj.w));                            \
    Vc.x = fmaf(c1.x, c2.x, fmaf(o1.x, -o2.x, Vc.x));                            \
    Vc.y = fmaf(c1.y, c2.y, fmaf(o1.y, -o2.y, Vc.y));                            \
    Vc.z = fmaf(c1.z, c2.z, fmaf(o1.z, -o2.z, Vc.z));                            \
    Vc.w = fmaf(c1.w, c2.w, fmaf(o1.w, -o2.w, Vc.w));                            \
    if (DO_OUT) {  /* output row i */                                            \
        float al  = __shfl_up_sync(0xffffffffu, Vi.w, 1);                        \
        float ar0 = __shfl_down_sync(0xffffffffu, Vi.x, 1);                      \
        float ar1 = __shfl_down_sync(0xffffffffu, Vi.y, 1);                      \
        float bl  = __shfl_up_sync(0xffffffffu, Vj.w, 1);                        \
        float br0 = __shfl_down_sync(0xffffffffu, Vj.x, 1);                      \
        float br1 = __shfl_down_sync(0xffffffffu, Vj.y, 1);                      \
        float cl  = __shfl_up_sync(0xffffffffu, Vc.w, 1);                        \
        float cr0 = __shfl_down_sync(0xffffffffu, Vc.x, 1);                      \
        float cr1 = __shfl_down_sync(0xffffffffu, Vc.y, 1);                      \
        float4 sii = hwin(Vi, al, ar0, ar1);                                     \
        float4 sjj = hwin(Vj, bl, br0, br1);                                     \
        float4 sij = hwin(Vc, cl, cr0, cr1);                                     \
        { float a = fmaxf(sii.x, 1e-20f), b = fmaxf(sjj.x, 1e-20f);              \
          float L = fmaxf(sij.x * rsqrtf(a * b), -1.f);                          \
          acc = fmaf(L, mOn, acc); }                                             \
        { float a = fmaxf(sii.y, 1e-20f), b = fmaxf(sjj.y, 1e-20f);              \
          float L = fmaxf(sij.y * rsqrtf(a * b), -1.f);                          \
          acc = fmaf(L, mOn, acc); }                                             \
        { float a = fmaxf(sii.z, 1e-20f), b = fmaxf(sjj.z, 1e-20f);              \
          float L = fmaxf(sij.z * rsqrtf(a * b), -1.f);                          \
          acc = fmaf(L, mOn, acc); }                                             \
        { float a = fmaxf(sii.w, 1e-20f), b = fmaxf(sjj.w, 1e-20f);              \
          float L = fmaxf(sij.w * rsqrtf(a * b), -1.f);                          \
          acc = fmaf(L, mOn, acc); }                                             \
    }                                                                            \
} while (0)

    // ---- warmup: 8 steps, no output ----
    STEP(0, i0 + 0, false, true); STEP(1, i0 + 1, false, true);
    STEP(2, i0 + 2, false, true); STEP(3, i0 + 3, false, true);
    STEP(4, i0 + 4, false, true); STEP(5, i0 + 5, false, true);
    STEP(6, i0 + 6, false, true); STEP(7, i0 + 7, false, true);
    pX += 8 * HN; pY += 8 * HN;

    // ---- steady: 7 groups of 8 output steps ----
#pragma unroll 1
    for (int T = 8; T < 64; T += 8) {
        STEP(0, i0 + T + 0, true, true); STEP(1, i0 + T + 1, true, true);
        STEP(2, i0 + T + 2, true, true); STEP(3, i0 + T + 3, true, true);
        STEP(4, i0 + T + 4, true, true); STEP(5, i0 + T + 5, true, true);
        STEP(6, i0 + T + 6, true, true); STEP(7, i0 + T + 7, true, true);
        pX += 8 * HN; pY += 8 * HN;
    }

    // ---- final group: last 4 steps need no new loads ----
    {
        const int T = 64;
        STEP(0, i0 + T + 0, true, true);  STEP(1, i0 + T + 1, true, true);
        STEP(2, i0 + T + 2, true, true);  STEP(3, i0 + T + 3, true, true);
        STEP(4, i0 + T + 4, true, false); STEP(5, i0 + T + 5, true, false);
        STEP(6, i0 + T + 6, true, false); STEP(7, i0 + T + 7, true, false);
    }
#undef STEP

    // +1 per valid output pixel, plus accumulated (-L)
    return fmaf((float)(TH * 4), mO, acc);
}

__global__ void __launch_bounds__(WPB * 32, 4)
xcorr_kernel(const float* __restrict__ X, const float* __restrict__ Y,
             float* __restrict__ out) {
    __shared__ float4 sc1[4][128];
    __shared__ float4 sc2[4][128];

    const int tid = threadIdx.x;
    const int lane = tid & 31;
    const int warp = tid >> 5;
    const int t = blockIdx.x * WPB + warp;   // 0..2367

    float tot;
    if (t < N_INT) {
        const int strip = 1 + t % 35;        // interior: strips 1..35, bands 1..62
        const int band = 1 + t / 35;
        tot = tile_compute<false>(X, Y, strip, band, lane, tid, sc1, sc2);
    } else {
        const int e = t - N_INT;             // 0..197 edge tiles
        int strip, band;
        if (e < 37)      { strip = e;       band = 0; }
        else if (e < 74) { strip = e - 37;  band = 63; }
        else { int e2 = e - 74; strip = (e2 & 1) ? 36 : 0; band = 1 + (e2 >> 1); }
        tot = tile_compute<true>(X, Y, strip, band, lane, tid, sc1, sc2);
    }

#pragma unroll
    for (int o = 16; o; o >>= 1) tot += __shfl_xor_sync(0xffffffffu, tot, o);

    __shared__ float wsum[WPB];
    if (lane == 0) wsum[warp] = tot;
    __syncthreads();
    if (threadIdx.x == 0) {
        float s = wsum[0] + wsum[1] + wsum[2] + wsum[3];
        atomicAdd(&g_accs[(blockIdx.x & 7) * 16], (double)s);
        __threadfence();
        unsigned done = atomicAdd(&g_done, 1u);
        if (done == (unsigned)(NBLK - 1)) {   // last block finalizes
            double m = 0.0;
#pragma unroll
            for (int k = 0; k < 8; ++k)
                m += atomicAdd(&g_accs[k * 16], 0.0);   // coherent read
            m *= (1.0 / ((double)HN * (double)HN));
            out[0] = (float)m;
            out[1] = (float)m;
#pragma unroll
            for (int k = 0; k < 8; ++k) g_accs[k * 16] = 0.0;  // reset for replay
            g_done = 0u;
        }
    }
}

extern "C" void kernel_launch(void* const* d_in, const int* in_sizes, int n_in,
                              void* d_out, int out_size) {
    const float* X = (const float*)d_in[0];   // outputs
    const float* Y = (const float*)d_in[1];   // labels
    xcorr_kernel<<<NBLK, WPB * 32>>>(X, Y, (float*)d_out);
}

// round 10
// speedup vs baseline: 1.0259x; 1.0259x over previous
#include <cuda_runtime.h>

#define HN 4096

constexpr int TH = 64;                     // output rows per warp-tile
constexpr int OUTW = 112;                  // output cols per warp strip
constexpr int NSTRIPS = 37;
constexpr int WPB = 4;
constexpr int NTILES = NSTRIPS * (HN / TH);   // 2368
constexpr int NBLK = NTILES / WPB;            // 592 = 4 * 148
constexpr int N_INT = 35 * 62;                // 2170 interior tiles

__device__ double g_accs[8 * 16];
__device__ unsigned g_done;

static __device__ __forceinline__ float4 ld4p(const float* p, bool v) {
    float4 r = make_float4(0.f, 0.f, 0.f, 0.f);
    if (v) r = *reinterpret_cast<const float4*>(p);
    return r;
}

// 4-tap window sum over columns: g[c] = v[c-1]+v[c]+v[c+1]+v[c+2]
static __device__ __forceinline__ float4 hwin(float4 v, float vl, float vr0, float vr1) {
    float4 g;
    g.x = vl + v.x + v.y + v.z;
    g.y = g.x - vl + v.w;
    g.z = g.y - v.x + vr0;
    g.w = g.z - v.y + vr1;
    return g;
}

static __device__ __forceinline__ float maskf(float x, unsigned m) {
    return __uint_as_float(__float_as_uint(x) & m);
}

template<bool EDGE>
static __device__ __forceinline__ float tile_compute(
    const float* __restrict__ X, const float* __restrict__ Y,
    int strip, int tyt, int lane)
{
    const int ty0 = tyt * TH;
    const long col0 = (long)strip * OUTW - 8 + 4 * lane;
    const bool ld_ok = EDGE ? ((col0 >= 0) && (col0 + 3 < HN)) : true;
    const unsigned mCb = EDGE ? ((lane >= 1 && lane <= 30 && ld_ok) ? ~0u : 0u) : ~0u;
    const float mO = ((lane >= 2 && lane <= 29) && ld_ok) ? 1.f : 0.f;
    const float mOn = -mO;
    const int i0 = ty0 - 8;

    // load base: at local step t the load targets row i0+6+t  ->  pX + t*HN
    const float* pX = X + col0 + (long)(i0 + 6) * HN;
    const float* pY = Y + col0 + (long)(i0 + 6) * HN;

    // 6-deep raw-row ring; at local step t: evict/load slot t%6,
    // x2 = slot (t+2)%6 (row i+2), xc = slot (t+4)%6 (row i+4).
    float4 rxr[6], ryr[6];
    const float4 z4 = make_float4(0.f, 0.f, 0.f, 0.f);
    rxr[0] = rxr[1] = rxr[2] = rxr[3] = z4;
    ryr[0] = ryr[1] = ryr[2] = ryr[3] = z4;
    {   // prefill slots 4,5 with rows i0+4, i0+5
        bool v4 = EDGE ? (ld_ok && (unsigned)(i0 + 4) < HN) : true;
        bool v5 = EDGE ? (ld_ok && (unsigned)(i0 + 5) < HN) : true;
        rxr[4] = ld4p(pX - 2 * HN, v4); ryr[4] = ld4p(pY - 2 * HN, v4);
        rxr[5] = ld4p(pX - 1 * HN, v5); ryr[5] = ld4p(pY - 1 * HN, v5);
    }

    // centered-value rings (registers), rolling sums
    float4 rc1[4], rc2[4];
    rc1[0] = rc1[1] = rc1[2] = rc1[3] = z4;
    rc2[0] = rc2[1] = rc2[2] = rc2[3] = z4;
    float4 Vx = z4, Vy = z4, Vi = z4, Vj = z4, Vc = z4;
    float acc = 0.f;

// One row-step. OFF = group-local load offset (0..11), A=t%6 (evict/load slot),
// B=(t+2)%6 (x2), C=(t+4)%6 (xc), RC=(t+2)&3, IROW=i (abs row), flags compile-time.
#define STEP(OFF, A, B, C, RC, IROW, DO_OUT, DO_LOAD) do {                       \
    float4 o1 = rc1[RC], o2 = rc2[RC];        /* evict-c (4 steps old) */        \
    float4 xo = rxr[A], yo = ryr[A];          /* evict raw row i */              \
    if (DO_LOAD) {                                                               \
        bool v = EDGE ? (ld_ok && (unsigned)((IROW) + 6) < HN) : true;           \
        rxr[A] = ld4p(pX + (long)(OFF) * HN, v);                                 \
        ryr[A] = ld4p(pY + (long)(OFF) * HN, v);                                 \
    }                                                                            \
    float4 xc = rxr[C], yc = ryr[C];          /* row i+4 (loaded 2 steps ago) */ \
    Vx.x += xc.x - xo.x; Vx.y += xc.y - xo.y;                                    \
    Vx.z += xc.z - xo.z; Vx.w += xc.w - xo.w;                                    \
    Vy.x += yc.x - yo.x; Vy.y += yc.y - yo.y;                                    \
    Vy.z += yc.z - yo.z; Vy.w += yc.w - yo.w;                                    \
    float4 x2 = rxr[B], y2 = ryr[B];          /* row i+2 */                      \
    float vlx  = __shfl_up_sync(0xffffffffu, Vx.w, 1);                           \
    float vrx0 = __shfl_down_sync(0xffffffffu, Vx.x, 1);                         \
    float vrx1 = __shfl_down_sync(0xffffffffu, Vx.y, 1);                         \
    float vly  = __shfl_up_sync(0xffffffffu, Vy.w, 1);                           \
    float vry0 = __shfl_down_sync(0xffffffffu, Vy.x, 1);                         \
    float vry1 = __shfl_down_sync(0xffffffffu, Vy.y, 1);                         \
    float4 mx = hwin(Vx, vlx, vrx0, vrx1);    /* 16*mu at row i+2 */             \
    float4 my = hwin(Vy, vly, vry0, vry1);                                       \
    unsigned rmask = EDGE ? (((unsigned)((IROW) + 2) < HN) ? mCb : 0u) : ~0u;    \
    float4 c1, c2;                                                               \
    c1.x = maskf(fmaf(mx.x, -0.0625f, x2.x), rmask);                             \
    c1.y = maskf(fmaf(mx.y, -0.0625f, x2.y), rmask);                             \
    c1.z = maskf(fmaf(mx.z, -0.0625f, x2.z), rmask);                             \
    c1.w = maskf(fmaf(mx.w, -0.0625f, x2.w), rmask);                             \
    c2.x = maskf(fmaf(my.x, -0.0625f, y2.x), rmask);                             \
    c2.y = maskf(fmaf(my.y, -0.0625f, y2.y), rmask);                             \
    c2.z = maskf(fmaf(my.z, -0.0625f, y2.z), rmask);                             \
    c2.w = maskf(fmaf(my.w, -0.0625f, y2.w), rmask);                             \
    rc1[RC] = c1; rc2[RC] = c2;                                                  \
    Vi.x = fmaf(c1.x, c1.x, fmaf(o1.x, -o1.x, Vi.x));                            \
    Vi.y = fmaf(c1.y, c1.y, fmaf(o1.y, -o1.y, Vi.y));                            \
    Vi.z = fmaf(c1.z, c1.z, fmaf(o1.z, -o1.z, Vi.z));                            \
    Vi.w = fmaf(c1.w, c1.w, fmaf(o1.w, -o1.w, Vi.w));                            \
    Vj.x = fmaf(c2.x, c2.x, fmaf(o2.x, -o2.x, Vj.x));                            \
    Vj.y = fmaf(c2.y, c2.y, fmaf(o2.y, -o2.y, Vj.y));                            \
    Vj.z = fmaf(c2.z, c2.z, fmaf(o2.z, -o2.z, Vj.z));                            \
    Vj.w = fmaf(c2.w, c2.w, fmaf(o2.w, -o2.w, Vj.w));                            \
    Vc.x = fmaf(c1.x, c2.x, fmaf(o1.x, -o2.x, Vc.x));                            \
    Vc.y = fmaf(c1.y, c2.y, fmaf(o1.y, -o2.y, Vc.y));                            \
    Vc.z = fmaf(c1.z, c2.z, fmaf(o1.z, -o2.z, Vc.z));                            \
    Vc.w = fmaf(c1.w, c2.w, fmaf(o1.w, -o2.w, Vc.w));                            \
    if (DO_OUT) {  /* output row i */                                            \
        float al  = __shfl_up_sync(0xffffffffu, Vi.w, 1);                        \
        float ar0 = __shfl_down_sync(0xffffffffu, Vi.x, 1);                      \
        float ar1 = __shfl_down_sync(0xffffffffu, Vi.y, 1);                      \
        float bl  = __shfl_up_sync(0xffffffffu, Vj.w, 1);                        \
        float br0 = __shfl_down_sync(0xffffffffu, Vj.x, 1);                      \
        float br1 = __shfl_down_sync(0xffffffffu, Vj.y, 1);                      \
        float cl  = __shfl_up_sync(0xffffffffu, Vc.w, 1);                        \
        float cr0 = __shfl_down_sync(0xffffffffu, Vc.x, 1);                      \
        float cr1 = __shfl_down_sync(0xffffffffu, Vc.y, 1);                      \
        float4 sii = hwin(Vi, al, ar0, ar1);                                     \
        float4 sjj = hwin(Vj, bl, br0, br1);                                     \
        float4 sij = hwin(Vc, cl, cr0, cr1);                                     \
        { float a = fmaxf(sii.x, 1e-20f), b = fmaxf(sjj.x, 1e-20f);              \
          float L = fmaxf(sij.x * rsqrtf(a * b), -1.f);                          \
          acc = fmaf(L, mOn, acc); }                                             \
        { float a = fmaxf(sii.y, 1e-20f), b = fmaxf(sjj.y, 1e-20f);              \
          float L = fmaxf(sij.y * rsqrtf(a * b), -1.f);                          \
          acc = fmaf(L, mOn, acc); }                                             \
        { float a = fmaxf(sii.z, 1e-20f), b = fmaxf(sjj.z, 1e-20f);              \
          float L = fmaxf(sij.z * rsqrtf(a * b), -1.f);                          \
          acc = fmaf(L, mOn, acc); }                                             \
        { float a = fmaxf(sii.w, 1e-20f), b = fmaxf(sjj.w, 1e-20f);              \
          float L = fmaxf(sij.w * rsqrtf(a * b), -1.f);                          \
          acc = fmaf(L, mOn, acc); }                                             \
    }                                                                            \
} while (0)

// A/B/C/RC pattern for t mod 12 = 0..11 (A=t%6, B=(t+2)%6, C=(t+4)%6, RC=(t+2)&3)
#define G0(T, O0, O1, O2, O3)  \
    STEP(0, 0, 2, 4, 2, i0 + (T) + 0, O0, true);  \
    STEP(1, 1, 3, 5, 3, i0 + (T) + 1, O1, true);  \
    STEP(2, 2, 4, 0, 0, i0 + (T) + 2, O2, true);  \
    STEP(3, 3, 5, 1, 1, i0 + (T) + 3, O3, true)
#define G1(T, LD10, LD11)  \
    STEP(4,  4, 0, 2, 2, i0 + (T) + 4,  true, true);   \
    STEP(5,  5, 1, 3, 3, i0 + (T) + 5,  true, true);   \
    STEP(6,  0, 2, 4, 0, i0 + (T) + 6,  true, true);   \
    STEP(7,  1, 3, 5, 1, i0 + (T) + 7,  true, true);   \
    STEP(8,  2, 4, 0, 2, i0 + (T) + 8,  true, true);   \
    STEP(9,  3, 5, 1, 3, i0 + (T) + 9,  true, true);   \
    STEP(10, 4, 0, 2, 0, i0 + (T) + 10, true, LD10);   \
    STEP(11, 5, 1, 3, 1, i0 + (T) + 11, true, LD11)

    // ---- group 0: t=0..11 (first 8 steps no output) ----
    STEP(0, 0, 2, 4, 2, i0 + 0, false, true);
    STEP(1, 1, 3, 5, 3, i0 + 1, false, true);
    STEP(2, 2, 4, 0, 0, i0 + 2, false, true);
    STEP(3, 3, 5, 1, 1, i0 + 3, false, true);
    STEP(4, 4, 0, 2, 2, i0 + 4, false, true);
    STEP(5, 5, 1, 3, 3, i0 + 5, false, true);
    STEP(6, 0, 2, 4, 0, i0 + 6, false, true);
    STEP(7, 1, 3, 5, 1, i0 + 7, false, true);
    STEP(8,  2, 4, 0, 2, i0 + 8,  true, true);
    STEP(9,  3, 5, 1, 3, i0 + 9,  true, true);
    STEP(10, 4, 0, 2, 0, i0 + 10, true, true);
    STEP(11, 5, 1, 3, 1, i0 + 11, true, true);
    pX += 12 * HN; pY += 12 * HN;

    // ---- steady: 4 groups of 12 output steps ----
#pragma unroll 1
    for (int T = 12; T < 60; T += 12) {
        G0(T, true, true, true, true);
        G1(T, true, true);
        pX += 12 * HN; pY += 12 * HN;
    }

    // ---- final group: t=60..71; loads at t=70,71 are dead ----
    G0(60, true, true, true, true);
    G1(60, false, false);

#undef G0
#undef G1
#undef STEP

    return fmaf((float)(TH * 4), mO, acc);   // +1 per valid output pixel, -L accumulated
}

__global__ void __launch_bounds__(WPB * 32, 4)
xcorr_kernel(const float* __restrict__ X, const float* __restrict__ Y,
             float* __restrict__ out) {
    const int lane = threadIdx.x & 31;
    const int warp = threadIdx.x >> 5;
    const int t = blockIdx.x * WPB + warp;   // 0..2367

    float tot;
    if (t < N_INT) {
        const int strip = 1 + t % 35;        // interior: strips 1..35, bands 1..62
        const int band = 1 + t / 35;
        tot = tile_compute<false>(X, Y, strip, band, lane);
    } else {
        const int e = t - N_INT;             // 0..197 edge tiles
        int strip, band;
        if (e < 37)      { strip = e;       band = 0; }
        else if (e < 74) { strip = e - 37;  band = 63; }
        else { int e2 = e - 74; strip = (e2 & 1) ? 36 : 0; band = 1 + (e2 >> 1); }
        tot = tile_compute<true>(X, Y, strip, band, lane);
    }

#pragma unroll
    for (int o = 16; o; o >>= 1) tot += __shfl_xor_sync(0xffffffffu, tot, o);

    __shared__ float wsum[WPB];
    if (lane == 0) wsum[warp] = tot;
    __syncthreads();
    if (threadIdx.x == 0) {
        float s = wsum[0] + wsum[1] + wsum[2] + wsum[3];
        atomicAdd(&g_accs[(blockIdx.x & 7) * 16], (double)s);
        __threadfence();
        unsigned done = atomicAdd(&g_done, 1u);
        if (done == (unsigned)(NBLK - 1)) {   // last block finalizes
            double m = 0.0;
#pragma unroll
            for (int k = 0; k < 8; ++k)
                m += atomicAdd(&g_accs[k * 16], 0.0);   // coherent read
            m *= (1.0 / ((double)HN * (double)HN));
            out[0] = (float)m;
            out[1] = (float)m;
#pragma unroll
            for (int k = 0; k < 8; ++k) g_accs[k * 16] = 0.0;  // reset for replay
            g_done = 0u;
        }
    }
}

extern "C" void kernel_launch(void* const* d_in, const int* in_sizes, int n_in,
                              void* d_out, int out_size) {
    const float* X = (const float*)d_in[0];   // outputs
    const float* Y = (const float*)d_in[1];   // labels
    xcorr_kernel<<<NBLK, WPB * 32>>>(X, Y, (float*)d_out);
}